// round 2
// baseline (speedup 1.0000x reference)
#include <cuda_runtime.h>
#include <math_constants.h>
#include <cstdint>

// VectorQuantizer: latents [131072, 64] f32, codebook [512, 64] f32.
// Output layout (f32): quantized_st[8388608] | codes[131072] | commitment*0.25 | codebook_loss | perplexity

#define D        64
#define K        512
#define N_VEC    131072
#define TPB      256
#define VEC_PER_BLK 256
#define NBLK     (N_VEC / VEC_PER_BLK)   // 512

#define OUT_Q      0
#define OUT_CODES  (N_VEC * D)                 // 8388608
#define OUT_SCAL   (OUT_CODES + N_VEC)         // 8519680

__device__ double g_mse_sum;
__device__ int    g_hist[K];

__global__ void vq_init_kernel() {
    int t = blockIdx.x * blockDim.x + threadIdx.x;
    if (t == 0) g_mse_sum = 0.0;
    if (t < K) g_hist[t] = 0;
}

// Shared layout (floats): cb[K*D] | tile[VEC_PER_BLK*D] | c2[K] | red[32]
#define SM_CB    0
#define SM_TILE  (K * D)
#define SM_C2    (SM_TILE + VEC_PER_BLK * D)
#define SM_RED   (SM_C2 + K)
#define SM_FLOATS (SM_RED + 32)

__global__ __launch_bounds__(TPB) void vq_main_kernel(
    const float* __restrict__ latents,
    const float* __restrict__ codebook,
    float* __restrict__ out)
{
    extern __shared__ float sm[];
    float* cb   = sm + SM_CB;
    float* tile = sm + SM_TILE;
    float* c2s  = sm + SM_C2;
    float* red  = sm + SM_RED;

    const int tid = threadIdx.x;

    // ---- Stage codebook (coalesced, 128 KB) ----
    {
        const float4* g = (const float4*)codebook;
        float4* s = (float4*)cb;
        #pragma unroll 4
        for (int i = tid; i < K * D / 4; i += TPB) s[i] = g[i];
    }
    // ---- Stage latent tile (coalesced, 64 KB) ----
    {
        const float4* g = (const float4*)latents + (size_t)blockIdx.x * (VEC_PER_BLK * D / 4);
        float4* s = (float4*)tile;
        #pragma unroll 4
        for (int i = tid; i < VEC_PER_BLK * D / 4; i += TPB) s[i] = g[i];
    }
    __syncthreads();

    // ---- c2[k] = sum_d cb[k][d]^2 ----
    for (int k = tid; k < K; k += TPB) {
        const float4* row = (const float4*)(cb + k * D);
        float4 a = make_float4(0.f, 0.f, 0.f, 0.f);
        #pragma unroll
        for (int i = 0; i < D / 4; i++) {
            float4 c = row[i];
            a.x = fmaf(c.x, c.x, a.x);
            a.y = fmaf(c.y, c.y, a.y);
            a.z = fmaf(c.z, c.z, a.z);
            a.w = fmaf(c.w, c.w, a.w);
        }
        c2s[k] = (a.x + a.y) + (a.z + a.w);
    }
    __syncthreads();

    // ---- Load my vector into registers ----
    float4 x4[D / 4];
    {
        const float4* myx = (const float4*)(tile + tid * D);
        #pragma unroll
        for (int i = 0; i < D / 4; i++) x4[i] = myx[i];
    }

    // ---- x2 = ||x||^2 ----
    float x2;
    {
        float4 a = make_float4(0.f, 0.f, 0.f, 0.f);
        #pragma unroll
        for (int i = 0; i < D / 4; i++) {
            a.x = fmaf(x4[i].x, x4[i].x, a.x);
            a.y = fmaf(x4[i].y, x4[i].y, a.y);
            a.z = fmaf(x4[i].z, x4[i].z, a.z);
            a.w = fmaf(x4[i].w, x4[i].w, a.w);
        }
        x2 = (a.x + a.y) + (a.z + a.w);
    }

    // ---- Argmin over 512 codes: d2 = (x2 - 2*dot) + c2  (reference op order) ----
    float best = CUDART_INF_F;
    int bestk = 0;
    const float4* cbv = (const float4*)cb;
    #pragma unroll 2
    for (int k = 0; k < K; k++) {
        const float4* row = cbv + k * (D / 4);
        float4 acc = make_float4(0.f, 0.f, 0.f, 0.f);
        #pragma unroll
        for (int i = 0; i < D / 4; i++) {
            float4 c = row[i];
            acc.x = fmaf(x4[i].x, c.x, acc.x);
            acc.y = fmaf(x4[i].y, c.y, acc.y);
            acc.z = fmaf(x4[i].z, c.z, acc.z);
            acc.w = fmaf(x4[i].w, c.w, acc.w);
        }
        float dot = (acc.x + acc.y) + (acc.z + acc.w);
        float t = fmaf(-2.0f, dot, x2);   // == round(x2 - 2*dot), single rounding
        float d2 = t + c2s[k];
        if (d2 < best) { best = d2; bestk = k; }  // strict <: first-index tie-break
    }

    // ---- Quantized output (straight-through value: x + (q - x)), mse, code ----
    const int v = blockIdx.x * VEC_PER_BLK + tid;
    float msq = 0.f;
    {
        const float4* q4 = (const float4*)(cb + bestk * D);
        float4* myq = (float4*)(tile + tid * D);   // overwrite own region
        #pragma unroll
        for (int i = 0; i < D / 4; i++) {
            float4 c = q4[i];
            float4 xv = x4[i];
            float4 o;
            o.x = xv.x + (c.x - xv.x);
            o.y = xv.y + (c.y - xv.y);
            o.z = xv.z + (c.z - xv.z);
            o.w = xv.w + (c.w - xv.w);
            float dx = xv.x - c.x; msq = fmaf(dx, dx, msq);
            dx = xv.y - c.y; msq = fmaf(dx, dx, msq);
            dx = xv.z - c.z; msq = fmaf(dx, dx, msq);
            dx = xv.w - c.w; msq = fmaf(dx, dx, msq);
            myq[i] = o;
        }
    }
    out[OUT_CODES + v] = (float)bestk;
    atomicAdd(&g_hist[bestk], 1);

    // ---- Block-reduce msq -> global double ----
    {
        #pragma unroll
        for (int s = 16; s > 0; s >>= 1)
            msq += __shfl_xor_sync(0xFFFFFFFFu, msq, s);
        int wid = tid >> 5, lid = tid & 31;
        if (lid == 0) red[wid] = msq;
        __syncthreads();
        if (tid == 0) {
            float bsum = 0.f;
            #pragma unroll
            for (int w = 0; w < TPB / 32; w++) bsum += red[w];
            atomicAdd(&g_mse_sum, (double)bsum);
        }
    }
    __syncthreads();  // tile fully written by all threads before cooperative store

    // ---- Cooperative coalesced store of quantized_st ----
    {
        float4* og = (float4*)(out + OUT_Q) + (size_t)blockIdx.x * (VEC_PER_BLK * D / 4);
        const float4* s = (const float4*)tile;
        #pragma unroll 4
        for (int i = tid; i < VEC_PER_BLK * D / 4; i += TPB) og[i] = s[i];
    }
}

__global__ void vq_finalize_kernel(float* __restrict__ out) {
    __shared__ float sh[K];
    int t = threadIdx.x;
    float cnt = (float)g_hist[t];
    float p = cnt / (float)N_VEC;
    sh[t] = -p * logf(p + 1e-10f);
    __syncthreads();
    for (int s = K / 2; s > 0; s >>= 1) {
        if (t < s) sh[t] += sh[t + s];
        __syncthreads();
    }
    if (t == 0) {
        float entropy = sh[0];
        float perplexity = expf(entropy);
        double mse = g_mse_sum / (double)(N_VEC * D);
        out[OUT_SCAL + 0] = (float)(mse * 0.25);   // commitment * COMMITMENT_COST
        out[OUT_SCAL + 1] = (float)mse;            // codebook_loss (same value)
        out[OUT_SCAL + 2] = perplexity;
    }
}

extern "C" void kernel_launch(void* const* d_in, const int* in_sizes, int n_in,
                              void* d_out, int out_size) {
    const float* latents  = (const float*)d_in[0];
    const float* codebook = (const float*)d_in[1];
    float* out = (float*)d_out;

    size_t smem = SM_FLOATS * sizeof(float);   // ~198.8 KB
    cudaFuncSetAttribute(vq_main_kernel,
                         cudaFuncAttributeMaxDynamicSharedMemorySize, (int)smem);

    vq_init_kernel<<<2, 256>>>();
    vq_main_kernel<<<NBLK, TPB, smem>>>(latents, codebook, out);
    vq_finalize_kernel<<<1, K>>>(out);
}

// round 5
// speedup vs baseline: 1.2916x; 1.2916x over previous
#include <cuda_runtime.h>
#include <cuda_bf16.h>
#include <math_constants.h>
#include <cstdint>

// VectorQuantizer on GB300 (sm_103 plain target): mma.sync bf16 screen + exact fp32 rescore.
// latents [131072,64] f32, codebook [512,64] f32.
// out (f32): quantized_st[8388608] | codes[131072] | commitment | codebook_loss | perplexity

#define D        64
#define K        512
#define N_VEC    131072
#define TILE_M   128
#define N_TILES  (N_VEC / TILE_M)   // 1024
#define TPB      256
#define GRID     148

#define OUT_CODES (N_VEC * D)
#define OUT_SCAL  (OUT_CODES + N_VEC)
#define MARGIN    4e-3f

// ---- smem byte layout ----
#define SM_RED     0                      // 8 floats
#define SM_X2      64                     // 128 f32
#define SM_BESTK   576                    // 128 i32
#define SM_C2      1088                   // 512 f32
#define SM_HIST    3136                   // 512 i32
#define SM_A_BF16  5248                   // 128 rows x 72 bf16 (144B stride)
#define SM_B_BF16  (SM_A_BF16 + 128*144)  // 23680: 512 rows x 72 bf16
#define SM_A_F32   (SM_B_BF16 + 512*144)  // 97408: 128 rows x 68 f32
#define A_STRIDE   68
#define SM_TOTAL   (SM_A_F32 + 128*A_STRIDE*4)   // 132224 bytes

__device__ double g_mse_sum;
__device__ int    g_hist[K];

__global__ void vq_init_kernel() {
    int t = blockIdx.x * blockDim.x + threadIdx.x;
    if (t == 0) g_mse_sum = 0.0;
    if (t < K) g_hist[t] = 0;
}

__device__ __forceinline__ void mma16816(float& c0, float& c1, float& c2, float& c3,
                                         uint32_t a0, uint32_t a1, uint32_t a2, uint32_t a3,
                                         uint32_t b0, uint32_t b1) {
    asm volatile(
        "mma.sync.aligned.m16n8k16.row.col.f32.bf16.bf16.f32 "
        "{%0,%1,%2,%3}, {%4,%5,%6,%7}, {%8,%9}, {%0,%1,%2,%3};"
        : "+f"(c0), "+f"(c1), "+f"(c2), "+f"(c3)
        : "r"(a0), "r"(a1), "r"(a2), "r"(a3), "r"(b0), "r"(b1));
}

__global__ __launch_bounds__(TPB) void vq_main_kernel(
    const float* __restrict__ latents,
    const float* __restrict__ codebook,
    float* __restrict__ out)
{
    extern __shared__ char smc[];
    float* red     = (float*)(smc + SM_RED);
    float* x2s     = (float*)(smc + SM_X2);
    int*   bestksm = (int*)(smc + SM_BESTK);
    float* c2s     = (float*)(smc + SM_C2);
    int*   histsm  = (int*)(smc + SM_HIST);
    float* a_f32   = (float*)(smc + SM_A_F32);

    const int tid  = threadIdx.x;
    const int wid  = tid >> 5;
    const int lane = tid & 31;
    const int g    = lane >> 2;     // group id 0..7
    const int tig  = lane & 3;      // thread-in-group
    const int rowbase = wid * 16;

    // ---- one-time setup: hist, B = -2*cb in bf16 (padded stride 72), c2 ----
    for (int k = tid; k < K; k += TPB) histsm[k] = 0;
    for (int idx = tid; idx < K * D; idx += TPB) {
        int k = idx >> 6, d = idx & 63;
        *(__nv_bfloat16*)(smc + SM_B_BF16 + k * 144 + d * 2) =
            __float2bfloat16_rn(-2.0f * codebook[idx]);
    }
    for (int k = tid; k < K; k += TPB) {   // Round-1-identical c2 formula
        const float4* row = (const float4*)(codebook + k * D);
        float4 a = make_float4(0.f, 0.f, 0.f, 0.f);
        #pragma unroll
        for (int i = 0; i < 16; i++) {
            float4 c = row[i];
            a.x = fmaf(c.x, c.x, a.x); a.y = fmaf(c.y, c.y, a.y);
            a.z = fmaf(c.z, c.z, a.z); a.w = fmaf(c.w, c.w, a.w);
        }
        c2s[k] = (a.x + a.y) + (a.z + a.w);
    }
    __syncthreads();

    float cta_msq = 0.f;

    for (int tile = blockIdx.x; tile < N_TILES; tile += gridDim.x) {
        // ---- 1. load latent tile: f32 staging + bf16 MMA operand ----
        {
            const float4* gp = (const float4*)latents + (size_t)tile * (TILE_M * D / 4);
            #pragma unroll
            for (int i = 0; i < 8; i++) {
                int idx = i * TPB + tid;
                float4 v = gp[idx];
                int row = idx >> 4, col = idx & 15;
                *(float4*)(a_f32 + row * A_STRIDE + col * 4) = v;
                __nv_bfloat162 b0 = __floats2bfloat162_rn(v.x, v.y);
                __nv_bfloat162 b1 = __floats2bfloat162_rn(v.z, v.w);
                uint2 u;
                u.x = *reinterpret_cast<unsigned*>(&b0);
                u.y = *reinterpret_cast<unsigned*>(&b1);
                *(uint2*)(smc + SM_A_BF16 + row * 144 + col * 8) = u;
            }
        }
        __syncthreads();

        // ---- 2. x2 per row (R1-identical formula) ----
        if (tid < TILE_M) {
            const float* my = a_f32 + tid * A_STRIDE;
            float4 a = make_float4(0.f, 0.f, 0.f, 0.f);
            #pragma unroll
            for (int i = 0; i < 16; i++) {
                float4 v = *(const float4*)(my + i * 4);
                a.x = fmaf(v.x, v.x, a.x); a.y = fmaf(v.y, v.y, a.y);
                a.z = fmaf(v.z, v.z, a.z); a.w = fmaf(v.w, v.w, a.w);
            }
            x2s[tid] = (a.x + a.y) + (a.z + a.w);
        }

        // ---- 3. A fragments for this warp's 16 rows (kept in regs) ----
        uint32_t af[4][4];
        #pragma unroll
        for (int kt = 0; kt < 4; kt++) {
            int kb = kt * 32 + tig * 4;   // byte offset within row: (kt*16 + 2*tig) * 2
            af[kt][0] = *(const uint32_t*)(smc + SM_A_BF16 + (rowbase + g)     * 144 + kb);
            af[kt][1] = *(const uint32_t*)(smc + SM_A_BF16 + (rowbase + g + 8) * 144 + kb);
            af[kt][2] = *(const uint32_t*)(smc + SM_A_BF16 + (rowbase + g)     * 144 + kb + 16);
            af[kt][3] = *(const uint32_t*)(smc + SM_A_BF16 + (rowbase + g + 8) * 144 + kb + 16);
        }
        __syncthreads();   // x2s visible to all before rescore phase

        // ---- 4. MMA screen: running min + candidate bitmasks ----
        float runA = CUDART_INF_F, runB = CUDART_INF_F;
        unsigned maskA[4], maskB[4];
        #pragma unroll
        for (int w4 = 0; w4 < 4; w4++) {
            unsigned mA = 0, mB = 0;
            #pragma unroll 4
            for (int i = 0; i < 16; i++) {
                int ntile = w4 * 16 + i;
                const char* bb = smc + SM_B_BF16 + (ntile * 8 + g) * 144 + tig * 4;
                float c0 = 0.f, c1 = 0.f, c2v = 0.f, c3 = 0.f;
                #pragma unroll
                for (int kt = 0; kt < 4; kt++) {
                    uint32_t b0 = *(const uint32_t*)(bb + kt * 32);
                    uint32_t b1 = *(const uint32_t*)(bb + kt * 32 + 16);
                    mma16816(c0, c1, c2v, c3, af[kt][0], af[kt][1], af[kt][2], af[kt][3], b0, b1);
                }
                float2 cp = *(const float2*)(c2s + ntile * 8 + tig * 2);
                float s0 = c0 + cp.x, s1 = c1 + cp.y;
                float s2 = c2v + cp.x, s3 = c3 + cp.y;
                runA = fminf(runA, fminf(s0, s1));
                runB = fminf(runB, fminf(s2, s3));
                float thrA = runA + MARGIN, thrB = runB + MARGIN;
                unsigned bitsA = (s0 < thrA ? 1u : 0u) | (s1 < thrA ? 2u : 0u);
                unsigned bitsB = (s2 < thrB ? 1u : 0u) | (s3 < thrB ? 2u : 0u);
                mA |= bitsA << (2 * i);
                mB |= bitsB << (2 * i);
            }
            maskA[w4] = mA; maskB[w4] = mB;
        }

        // ---- 5. exact fp32 rescore (R1-identical math), rows g and g+8 ----
        const int rowA = rowbase + g, rowB = rowbase + g + 8;
        const float x2A = x2s[rowA], x2B = x2s[rowB];
        const float* xA = a_f32 + rowA * A_STRIDE;
        const float* xB = a_f32 + rowB * A_STRIDE;
        float bestA = CUDART_INF_F, bestB = CUDART_INF_F;
        int bkA = 0, bkB = 0;
        #pragma unroll
        for (int w4 = 0; w4 < 4; w4++) {
            unsigned m = maskA[w4];
            while (m) {
                int b = __ffs(m) - 1; m &= m - 1;
                int col = (w4 * 16 + (b >> 1)) * 8 + tig * 2 + (b & 1);
                const float4* cr = (const float4*)(codebook + col * D);
                float4 acc = make_float4(0.f, 0.f, 0.f, 0.f);
                #pragma unroll
                for (int i = 0; i < 16; i++) {
                    float4 cc = cr[i];
                    float4 xv = *(const float4*)(xA + i * 4);
                    acc.x = fmaf(xv.x, cc.x, acc.x); acc.y = fmaf(xv.y, cc.y, acc.y);
                    acc.z = fmaf(xv.z, cc.z, acc.z); acc.w = fmaf(xv.w, cc.w, acc.w);
                }
                float dot = (acc.x + acc.y) + (acc.z + acc.w);
                float d2 = fmaf(-2.0f, dot, x2A) + c2s[col];
                if (d2 < bestA) { bestA = d2; bkA = col; }
            }
            m = maskB[w4];
            while (m) {
                int b = __ffs(m) - 1; m &= m - 1;
                int col = (w4 * 16 + (b >> 1)) * 8 + tig * 2 + (b & 1);
                const float4* cr = (const float4*)(codebook + col * D);
                float4 acc = make_float4(0.f, 0.f, 0.f, 0.f);
                #pragma unroll
                for (int i = 0; i < 16; i++) {
                    float4 cc = cr[i];
                    float4 xv = *(const float4*)(xB + i * 4);
                    acc.x = fmaf(xv.x, cc.x, acc.x); acc.y = fmaf(xv.y, cc.y, acc.y);
                    acc.z = fmaf(xv.z, cc.z, acc.z); acc.w = fmaf(xv.w, cc.w, acc.w);
                }
                float dot = (acc.x + acc.y) + (acc.z + acc.w);
                float d2 = fmaf(-2.0f, dot, x2B) + c2s[col];
                if (d2 < bestB) { bestB = d2; bkB = col; }
            }
        }

        // ---- 6. quad-reduce (d2, k) lexicographic: first-index tie-break ----
        #pragma unroll
        for (int off = 1; off <= 2; off <<= 1) {
            float odA = __shfl_xor_sync(0xFFFFFFFFu, bestA, off);
            int   okA = __shfl_xor_sync(0xFFFFFFFFu, bkA, off);
            if (odA < bestA || (odA == bestA && okA < bkA)) { bestA = odA; bkA = okA; }
            float odB = __shfl_xor_sync(0xFFFFFFFFu, bestB, off);
            int   okB = __shfl_xor_sync(0xFFFFFFFFu, bkB, off);
            if (odB < bestB || (odB == bestB && okB < bkB)) { bestB = odB; bkB = okB; }
        }
        if (tig == 0) {
            bestksm[rowA] = bkA;
            bestksm[rowB] = bkB;
        }
        __syncthreads();

        // ---- 7. codes + histogram ----
        if (tid < TILE_M) {
            int bk = bestksm[tid];
            out[OUT_CODES + tile * TILE_M + tid] = (float)bk;
            atomicAdd(&histsm[bk], 1);
        }

        // ---- 8. quantized_st store + mse (R1-identical elementwise math) ----
        float msq = 0.f;
        {
            float4* og = (float4*)out + (size_t)tile * (TILE_M * D / 4);
            #pragma unroll
            for (int i = 0; i < 8; i++) {
                int idx = i * TPB + tid;
                int row = idx >> 4, col = idx & 15;
                float4 xv = *(const float4*)(a_f32 + row * A_STRIDE + col * 4);
                float4 c = ((const float4*)(codebook + bestksm[row] * D))[col];
                float4 o;
                o.x = xv.x + (c.x - xv.x); o.y = xv.y + (c.y - xv.y);
                o.z = xv.z + (c.z - xv.z); o.w = xv.w + (c.w - xv.w);
                float dx = xv.x - c.x; msq = fmaf(dx, dx, msq);
                dx = xv.y - c.y; msq = fmaf(dx, dx, msq);
                dx = xv.z - c.z; msq = fmaf(dx, dx, msq);
                dx = xv.w - c.w; msq = fmaf(dx, dx, msq);
                og[idx] = o;
            }
        }

        // ---- 9. msq block-reduce ----
        #pragma unroll
        for (int s = 16; s > 0; s >>= 1) msq += __shfl_xor_sync(0xFFFFFFFFu, msq, s);
        if (lane == 0) red[wid] = msq;
        __syncthreads();
        if (tid == 0) {
            float bsum = 0.f;
            #pragma unroll
            for (int w = 0; w < 8; w++) bsum += red[w];
            cta_msq += bsum;
        }
        __syncthreads();   // protect a_f32 / a_bf16 / bestksm reuse next tile
    }

    // ---- flush per-CTA hist + mse ----
    for (int k = tid; k < K; k += TPB) {
        int h = histsm[k];
        if (h) atomicAdd(&g_hist[k], h);
    }
    if (tid == 0) atomicAdd(&g_mse_sum, (double)cta_msq);
}

__global__ void vq_finalize_kernel(float* __restrict__ out) {
    __shared__ float sh[K];
    int t = threadIdx.x;
    float cnt = (float)g_hist[t];
    float p = cnt / (float)N_VEC;
    sh[t] = -p * logf(p + 1e-10f);
    __syncthreads();
    for (int s = K / 2; s > 0; s >>= 1) {
        if (t < s) sh[t] += sh[t + s];
        __syncthreads();
    }
    if (t == 0) {
        float perplexity = expf(sh[0]);
        double mse = g_mse_sum / (double)(N_VEC * D);
        out[OUT_SCAL + 0] = (float)(mse * 0.25);
        out[OUT_SCAL + 1] = (float)mse;
        out[OUT_SCAL + 2] = perplexity;
    }
}

extern "C" void kernel_launch(void* const* d_in, const int* in_sizes, int n_in,
                              void* d_out, int out_size) {
    const float* latents  = (const float*)d_in[0];
    const float* codebook = (const float*)d_in[1];
    float* out = (float*)d_out;

    cudaFuncSetAttribute(vq_main_kernel,
                         cudaFuncAttributeMaxDynamicSharedMemorySize, SM_TOTAL);

    vq_init_kernel<<<2, 256>>>();
    vq_main_kernel<<<GRID, TPB, SM_TOTAL>>>(latents, codebook, out);
    vq_finalize_kernel<<<1, K>>>(out);
}